// round 1
// baseline (speedup 1.0000x reference)
#include <cuda_runtime.h>
#include <math.h>

#define HW   4096
#define IMW  64
#define IMH  64

// ---------------- scratch (device globals; no allocations allowed) ----------------
__device__ __align__(16) float g_cat[436 * HW];
__device__ __align__(16) float g_w1t[436 * 64];
__device__ __align__(16) float g_w6t[64 * 432];
__device__ __align__(16) float g_buf0[64 * HW];
__device__ __align__(16) float g_buf1[64 * HW];
__device__ __align__(16) float g_off[432 * HW];
__device__ __align__(16) float g_qp[HW * 288];          // pixel-major [pix][288]
__device__ __align__(16) float g_kp[2 * HW * 288];      // [clip][pix][288]
__device__ __align__(16) float g_vp[2 * HW * 288];
__device__ __align__(16) float g_attnout[HW * 288];     // [pix][288]
__device__ __align__(16) float g_obuf[HW * 144];        // [pix][144]
__device__ __align__(16) float g_hbuf[HW * 288];        // [pix][288]

// ---------------- concat [q, vpw0, vpw1, flow0, flow1] -> 436 planes ----------------
__global__ void concat_kernel(const float* __restrict__ q, const float* __restrict__ w0,
                              const float* __restrict__ w1, const float* __restrict__ f0,
                              const float* __restrict__ f1)
{
    int i = blockIdx.x * 256 + threadIdx.x;
    if (i >= 436 * HW) return;
    int ch = i >> 12, pix = i & (HW - 1);
    float v;
    if (ch < 144)      v = q[i];
    else if (ch < 288) v = w0[i - 144 * HW];
    else if (ch < 432) v = w1[i - 288 * HW];
    else if (ch < 434) v = f0[(ch - 432) * HW + pix];
    else               v = f1[(ch - 434) * HW + pix];
    g_cat[i] = v;
}

// ---------------- small weight transpose: w[O][I] -> wt[I][O] ----------------
__global__ void transpose_w_kernel(const float* __restrict__ w, float* __restrict__ wt,
                                   int O, int I)
{
    int idx = blockIdx.x * 256 + threadIdx.x;
    if (idx < O * I) {
        int o = idx / I, i = idx - o * I;
        wt[i * O + o] = w[idx];
    }
}

// ---------------- tiled SGEMM: out[M=4096, N] = A[M, K] @ W[K, N] + bias ----------------
// AMODE 0: A channel-major  A[i*HW + pix]
// AMODE 1: A pixel-major    A[pix*K + i]
// ACT: 0 none | 1 lrelu(0.1) | 2 gelu(exact erf) | 3 offset epilogue (10*tanh + flow)
//      4 residual add (extra pixel-major, stride N)
// OMODE 0: pixel-major out[pix*N + n] | OMODE 1: channel-major out[n*HW + pix]
template<int BN, int AMODE, int ACT, int OMODE>
__global__ void gemm_kernel(const float* __restrict__ A, const float* __restrict__ Wm,
                            const float* __restrict__ bias, float* __restrict__ out,
                            const float* __restrict__ extra, int K, int N)
{
    constexpr int BM = 64, BK = 16;
    constexpr int TN = BN / 4;
    __shared__ __align__(16) float sA[BK][BM];
    __shared__ __align__(16) float sW[BK][BN];
    int tid = threadIdx.x;
    int tn = tid % TN, tm = tid / TN;       // tm in [0,16)
    int pix0 = blockIdx.x * BM;
    int n0 = blockIdx.y * BN;

    float acc[4][4];
#pragma unroll
    for (int i = 0; i < 4; i++)
#pragma unroll
        for (int j = 0; j < 4; j++) acc[i][j] = 0.f;

    int ktiles = (K + BK - 1) / BK;
    for (int kt = 0; kt < ktiles; kt++) {
        int i0 = kt * BK;
        __syncthreads();
        for (int idx = tid; idx < BK * BM; idx += blockDim.x) {
            int kk = idx >> 6, m = idx & 63;
            int i = i0 + kk;
            float v = 0.f;
            if (i < K) v = (AMODE == 0) ? A[(size_t)i * HW + pix0 + m]
                                        : A[(size_t)(pix0 + m) * K + i];
            sA[kk][m] = v;
        }
        for (int idx = tid; idx < BK * BN; idx += blockDim.x) {
            int kk = idx / BN, n = idx - kk * BN;
            int i = i0 + kk;
            float v = 0.f;
            if (i < K) v = Wm[(size_t)i * N + n0 + n];
            sW[kk][n] = v;
        }
        __syncthreads();
#pragma unroll
        for (int kk = 0; kk < BK; kk++) {
            float4 a4 = *(const float4*)&sA[kk][tm * 4];
            float4 w4 = *(const float4*)&sW[kk][tn * 4];
            float av[4] = {a4.x, a4.y, a4.z, a4.w};
            float wv[4] = {w4.x, w4.y, w4.z, w4.w};
#pragma unroll
            for (int i2 = 0; i2 < 4; i2++)
#pragma unroll
                for (int j = 0; j < 4; j++)
                    acc[i2][j] = fmaf(av[i2], wv[j], acc[i2][j]);
        }
    }

#pragma unroll
    for (int mi = 0; mi < 4; mi++) {
        int m = pix0 + tm * 4 + mi;
        float vals[4];
#pragma unroll
        for (int ni = 0; ni < 4; ni++) {
            int n = n0 + tn * 4 + ni;
            float v = acc[mi][ni] + bias[n];
            if (ACT == 1) {
                v = v >= 0.f ? v : 0.1f * v;
            } else if (ACT == 2) {
                v = 0.5f * v * (1.f + erff(v * 0.70710678118654752f));
            } else if (ACT == 3) {
                v = 10.f * tanhf(v);
                // even channel (y) += flow0 ch1; odd channel (x) += flow0 ch0
                v += (n & 1) ? extra[m] : extra[HW + m];
            } else if (ACT == 4) {
                v += extra[(size_t)m * N + n];
            }
            vals[ni] = v;
        }
        if (OMODE == 0) {
            float4 r = make_float4(vals[0], vals[1], vals[2], vals[3]);
            *(float4*)&out[(size_t)m * N + n0 + tn * 4] = r;
        } else {
#pragma unroll
            for (int ni = 0; ni < 4; ni++)
                out[(size_t)(n0 + tn * 4 + ni) * HW + m] = vals[ni];
        }
    }
}

// ---------------- 3x3 conv 64->64, pad 1, lrelu; smem halo + smem weights ----------------
__global__ void conv3x3_lrelu_kernel(const float* __restrict__ in, const float* __restrict__ w,
                                     const float* __restrict__ b, float* __restrict__ out)
{
    constexpr int TW = 32, TH = 8, OCB = 8;
    __shared__ float s_h[TH + 2][TW + 2];
    __shared__ float s_w[OCB * 576];
    int tid = threadIdx.x;
    int tx = tid & 31, ty = tid >> 5;
    int x0 = blockIdx.x * TW, y0 = blockIdx.y * TH;
    int ocg = blockIdx.z * OCB;

    for (int i = tid; i < OCB * 576; i += 256) s_w[i] = w[ocg * 576 + i];

    float acc[OCB];
#pragma unroll
    for (int o = 0; o < OCB; o++) acc[o] = b[ocg + o];

    for (int ic = 0; ic < 64; ic++) {
        __syncthreads();
        const float* ip = in + ic * HW;
        for (int i = tid; i < (TH + 2) * (TW + 2); i += 256) {
            int hy = i / (TW + 2), hx = i - hy * (TW + 2);
            int gy = y0 + hy - 1, gx = x0 + hx - 1;
            float v = 0.f;
            if (gy >= 0 && gy < IMH && gx >= 0 && gx < IMW) v = ip[gy * IMW + gx];
            s_h[hy][hx] = v;
        }
        __syncthreads();
        float vv[9];
#pragma unroll
        for (int ky = 0; ky < 3; ky++)
#pragma unroll
            for (int kx = 0; kx < 3; kx++) vv[ky * 3 + kx] = s_h[ty + ky][tx + kx];
#pragma unroll
        for (int o = 0; o < OCB; o++) {
            const float* wp = &s_w[o * 576 + ic * 9];
#pragma unroll
            for (int kk = 0; kk < 9; kk++) acc[o] = fmaf(vv[kk], wp[kk], acc[o]);
        }
    }
    int pix = (y0 + ty) * IMW + x0 + tx;
#pragma unroll
    for (int o = 0; o < OCB; o++) {
        float r = acc[o];
        out[(ocg + o) * HW + pix] = r >= 0.f ? r : 0.1f * r;
    }
}

// ---------------- fused deformable-attention kernel ----------------
// grid (32, 12 heads), block 128. One thread = one (head, pixel).
__global__ void __launch_bounds__(128) attn_kernel()
{
    int pix = blockIdx.x * 128 + threadIdx.x;
    int m = blockIdx.y;
    int y = pix >> 6, x = pix & 63;

    const float* qp = g_qp + (size_t)pix * 288 + m * 24;
    float4 q4[6];
#pragma unroll
    for (int j = 0; j < 6; j++) q4[j] = *(const float4*)(qp + j * 4);

    float sc[18];
    // ---- pass 1: scores from k ----
#pragma unroll
    for (int c = 0; c < 2; c++) {
        const float* kbase = g_kp + (size_t)c * HW * 288 + m * 24;
#pragma unroll
        for (int a = 0; a < 9; a++) {
            int s = c * 9 + a;
            int och = (((c * 12 + m) * 9) + a) * 2;
            float py = g_off[(size_t)och * HW + pix] + (float)(a / 3 - 1 + y);
            float px = g_off[(size_t)(och + 1) * HW + pix] + (float)(a % 3 - 1 + x);
            float fy = floorf(py), fx = floorf(px);
            int y0 = (int)fy, x0 = (int)fx;
            float wy1 = py - fy, wx1 = px - fx;
            float wy0 = 1.f - wy1, wx0 = 1.f - wx1;
            float dot = 0.f;
#pragma unroll
            for (int cr = 0; cr < 4; cr++) {
                int yy = y0 + (cr >> 1), xx = x0 + (cr & 1);
                float wt = ((cr >> 1) ? wy1 : wy0) * ((cr & 1) ? wx1 : wx0);
                if (yy >= 0 && yy < IMH && xx >= 0 && xx < IMW) {
                    const float4* kk4 = (const float4*)(kbase + (size_t)(yy * IMW + xx) * 288);
                    float d = 0.f;
#pragma unroll
                    for (int j = 0; j < 6; j++) {
                        float4 kv = kk4[j];
                        d = fmaf(q4[j].x, kv.x, d);
                        d = fmaf(q4[j].y, kv.y, d);
                        d = fmaf(q4[j].z, kv.z, d);
                        d = fmaf(q4[j].w, kv.w, d);
                    }
                    dot = fmaf(wt, d, dot);
                }
            }
            sc[s] = dot * 0.2041241452319315f;   // 24^-0.5
        }
    }
    // ---- softmax over 18 ----
    float mx = sc[0];
#pragma unroll
    for (int s = 1; s < 18; s++) mx = fmaxf(mx, sc[s]);
    float sum = 0.f;
#pragma unroll
    for (int s = 0; s < 18; s++) { sc[s] = expf(sc[s] - mx); sum += sc[s]; }
    float inv = 1.f / sum;

    // ---- pass 2: weighted v gather ----
    float4 acc[6];
#pragma unroll
    for (int j = 0; j < 6; j++) acc[j] = make_float4(0.f, 0.f, 0.f, 0.f);
#pragma unroll
    for (int c = 0; c < 2; c++) {
        const float* vbase = g_vp + (size_t)c * HW * 288 + m * 24;
#pragma unroll
        for (int a = 0; a < 9; a++) {
            int s = c * 9 + a;
            int och = (((c * 12 + m) * 9) + a) * 2;
            float py = g_off[(size_t)och * HW + pix] + (float)(a / 3 - 1 + y);
            float px = g_off[(size_t)(och + 1) * HW + pix] + (float)(a % 3 - 1 + x);
            float fy = floorf(py), fx = floorf(px);
            int y0 = (int)fy, x0 = (int)fx;
            float wy1 = py - fy, wx1 = px - fx;
            float wy0 = 1.f - wy1, wx0 = 1.f - wx1;
            float pw = sc[s] * inv;
#pragma unroll
            for (int cr = 0; cr < 4; cr++) {
                int yy = y0 + (cr >> 1), xx = x0 + (cr & 1);
                float wt = ((cr >> 1) ? wy1 : wy0) * ((cr & 1) ? wx1 : wx0);
                if (yy >= 0 && yy < IMH && xx >= 0 && xx < IMW) {
                    float w2 = pw * wt;
                    const float4* vv4 = (const float4*)(vbase + (size_t)(yy * IMW + xx) * 288);
#pragma unroll
                    for (int j = 0; j < 6; j++) {
                        float4 v = vv4[j];
                        acc[j].x = fmaf(w2, v.x, acc[j].x);
                        acc[j].y = fmaf(w2, v.y, acc[j].y);
                        acc[j].z = fmaf(w2, v.z, acc[j].z);
                        acc[j].w = fmaf(w2, v.w, acc[j].w);
                    }
                }
            }
        }
    }
    float* op = g_attnout + (size_t)pix * 288 + m * 24;
#pragma unroll
    for (int j = 0; j < 6; j++) *(float4*)(op + j * 4) = acc[j];
}

// ---------------- launcher ----------------
extern "C" void kernel_launch(void* const* d_in, const int* in_sizes, int n_in,
                              void* d_out, int out_size)
{
    const float* q     = (const float*)d_in[0];
    const float* k     = (const float*)d_in[1];
    const float* v     = (const float*)d_in[2];
    const float* vpw0  = (const float*)d_in[3];
    const float* vpw1  = (const float*)d_in[4];
    const float* flow0 = (const float*)d_in[5];
    const float* flow1 = (const float*)d_in[6];
    const float* wo1 = (const float*)d_in[7];  const float* bo1 = (const float*)d_in[8];
    const float* wo2 = (const float*)d_in[9];  const float* bo2 = (const float*)d_in[10];
    const float* wo3 = (const float*)d_in[11]; const float* bo3 = (const float*)d_in[12];
    const float* wo4 = (const float*)d_in[13]; const float* bo4 = (const float*)d_in[14];
    const float* wo5 = (const float*)d_in[15]; const float* bo5 = (const float*)d_in[16];
    const float* wo6 = (const float*)d_in[17]; const float* bo6 = (const float*)d_in[18];
    const float* wq  = (const float*)d_in[19]; const float* bq  = (const float*)d_in[20];
    const float* wk  = (const float*)d_in[21]; const float* bk  = (const float*)d_in[22];
    const float* wv  = (const float*)d_in[23]; const float* bv  = (const float*)d_in[24];
    const float* wp  = (const float*)d_in[25]; const float* bp  = (const float*)d_in[26];
    const float* wm1 = (const float*)d_in[27]; const float* bm1 = (const float*)d_in[28];
    const float* wm2 = (const float*)d_in[29]; const float* bm2 = (const float*)d_in[30];
    float* outp = (float*)d_out;
    (void)in_sizes; (void)n_in; (void)out_size; (void)bq; (void)flow1;

    float *p_cat, *p_w1t, *p_w6t, *p_b0, *p_b1, *p_off, *p_qp, *p_kp, *p_vp, *p_ao, *p_ob, *p_hb;
    cudaGetSymbolAddress((void**)&p_cat, g_cat);
    cudaGetSymbolAddress((void**)&p_w1t, g_w1t);
    cudaGetSymbolAddress((void**)&p_w6t, g_w6t);
    cudaGetSymbolAddress((void**)&p_b0,  g_buf0);
    cudaGetSymbolAddress((void**)&p_b1,  g_buf1);
    cudaGetSymbolAddress((void**)&p_off, g_off);
    cudaGetSymbolAddress((void**)&p_qp,  g_qp);
    cudaGetSymbolAddress((void**)&p_kp,  g_kp);
    cudaGetSymbolAddress((void**)&p_vp,  g_vp);
    cudaGetSymbolAddress((void**)&p_ao,  g_attnout);
    cudaGetSymbolAddress((void**)&p_ob,  g_obuf);
    cudaGetSymbolAddress((void**)&p_hb,  g_hbuf);

    // offset-predictor CNN
    concat_kernel<<<(436 * HW + 255) / 256, 256>>>(q, vpw0, vpw1, flow0, flow1);
    transpose_w_kernel<<<(64 * 436 + 255) / 256, 256>>>(wo1, p_w1t, 64, 436);
    transpose_w_kernel<<<(432 * 64 + 255) / 256, 256>>>(wo6, p_w6t, 432, 64);
    gemm_kernel<64, 0, 1, 1><<<dim3(64, 1), 256>>>(p_cat, p_w1t, bo1, p_b0, nullptr, 436, 64);
    conv3x3_lrelu_kernel<<<dim3(2, 8, 8), 256>>>(p_b0, wo2, bo2, p_b1);
    conv3x3_lrelu_kernel<<<dim3(2, 8, 8), 256>>>(p_b1, wo3, bo3, p_b0);
    conv3x3_lrelu_kernel<<<dim3(2, 8, 8), 256>>>(p_b0, wo4, bo4, p_b1);
    conv3x3_lrelu_kernel<<<dim3(2, 8, 8), 256>>>(p_b1, wo5, bo5, p_b0);
    gemm_kernel<72, 0, 3, 1><<<dim3(64, 6), 288>>>(p_b0, p_w6t, bo6, p_off, flow0, 64, 432);

    // q/k/v projections (pixel-major outputs)
    gemm_kernel<72, 0, 0, 0><<<dim3(64, 4), 288>>>(q, wq, bq, p_qp, nullptr, 144, 288);
    gemm_kernel<72, 0, 0, 0><<<dim3(64, 4), 288>>>(k,            wk, bk, p_kp,            nullptr, 144, 288);
    gemm_kernel<72, 0, 0, 0><<<dim3(64, 4), 288>>>(k + 144 * HW, wk, bk, p_kp + HW * 288, nullptr, 144, 288);
    gemm_kernel<72, 0, 0, 0><<<dim3(64, 4), 288>>>(v,            wv, bv, p_vp,            nullptr, 144, 288);
    gemm_kernel<72, 0, 0, 0><<<dim3(64, 4), 288>>>(v + 144 * HW, wv, bv, p_vp + HW * 288, nullptr, 144, 288);

    // deformable attention
    attn_kernel<<<dim3(32, 12), 128>>>();

    // output projection + MLP residual, final transposed write
    gemm_kernel<72, 1, 0, 0><<<dim3(64, 2), 288>>>(p_ao, wp, bp, p_ob, nullptr, 288, 144);
    gemm_kernel<72, 1, 2, 0><<<dim3(64, 4), 288>>>(p_ob, wm1, bm1, p_hb, nullptr, 144, 288);
    gemm_kernel<72, 1, 4, 1><<<dim3(64, 2), 288>>>(p_hb, wm2, bm2, outp, p_ob, 288, 144);
}